// round 9
// baseline (speedup 1.0000x reference)
#include <cuda_runtime.h>

#define W56   56
#define HW    3136
#define WC_N  32
#define C_N   256
#define GRP   8
#define NTHR  256
#define W4N   14               // float4 per row
#define P4    (W56 * W4N)      // 784 float4-pixels per (b,c) image

__device__ __forceinline__ float4 zf4() { return make_float4(0.f, 0.f, 0.f, 0.f); }
__device__ __forceinline__ float2 zf2() { return make_float2(0.f, 0.f); }

template<int I>
__device__ __forceinline__ float comp(const float4& v) {
    if constexpr (I == 0) return v.x;
    else if constexpr (I == 1) return v.y;
    else if constexpr (I == 2) return v.z;
    else return v.w;
}

// One x-row window around [w4, w4+4): covers indices [4-D, 7+D] of a virtual
// 12-float span starting at w4-4. For D<=2 the edges are float2 loads.
template<int D>
struct Row {
    float4 M;
    float4 L, R;     // D >= 3
    float2 Lh, Rh;   // D <= 2
    template<int I>
    __device__ __forceinline__ float get() const {
        if constexpr (I >= 4 && I < 8) return comp<I - 4>(M);
        else if constexpr (I < 4) {
            if constexpr (D <= 2) return (I == 2) ? Lh.x : Lh.y;   // I in {2,3}
            else                  return comp<I>(L);
        } else {
            if constexpr (D <= 2) return (I == 8) ? Rh.x : Rh.y;   // I in {8,9}
            else                  return comp<I - 8>(R);
        }
    }
};

template<int D>
__device__ __forceinline__ Row<D> load_row(const float* r, bool v, bool lv, bool rvx) {
    Row<D> o;
    o.M = v ? *(const float4*)r : zf4();
    if constexpr (D <= 2) {
        o.Lh = (v && lv)  ? *(const float2*)(r - 2) : zf2();
        o.Rh = (v && rvx) ? *(const float2*)(r + 4) : zf2();
    } else {
        o.L = (v && lv)  ? *(const float4*)(r - 4) : zf4();
        o.R = (v && rvx) ? *(const float4*)(r + 4) : zf4();
    }
    return o;
}

template<int D, int KW>
__device__ __forceinline__ void fma4(float4& acc, const float4& wk, const Row<D>& a) {
    constexpr int c = (KW - 1) * D;
    acc.x += wk.x * a.template get<4 + 0 + c>();
    acc.y += wk.y * a.template get<4 + 1 + c>();
    acc.z += wk.z * a.template get<4 + 2 + c>();
    acc.w += wk.w * a.template get<4 + 3 + c>();
}

template<int D>
__device__ __forceinline__ void lcd_body(const float* __restrict__ x,
                                         const float* __restrict__ weight,
                                         float* __restrict__ out,
                                         int b, int wc, int h, int w4)
{
    // 9 taps × 4 pixels of weights in registers, reused across all 8 channel groups
    float4 wg[9];
    {
        const float* wp = weight + ((size_t)(b * WC_N + wc) * 9) * HW + h * W56 + w4;
#pragma unroll
        for (int k = 0; k < 9; k++) wg[k] = *(const float4*)(wp + k * HW);
    }

    const bool lv = (w4 > 0), rvx = (w4 < 52);
    bool rv[3];
    int  roff[3];
#pragma unroll
    for (int j = 0; j < 3; j++) {
        const int hh = h + (j - 1) * D;
        rv[j]   = (unsigned)hh < (unsigned)W56;
        roff[j] = hh * W56 + w4;
    }

    const float* xb = x   + (size_t)(b * C_N + wc) * HW;
    float*       ob = out + (size_t)(b * C_N + wc) * HW + h * W56 + w4;

#pragma unroll 1
    for (int g = 0; g < GRP; g += 2) {
        const float* xp0 = xb + (size_t)g * WC_N * HW;
        const float* xp1 = xp0 + (size_t)WC_N * HW;
        float4 acc0 = zf4(), acc1 = zf4();
#pragma unroll
        for (int j = 0; j < 3; j++) {
            // 6 independent loads (both g-streams) for this tap row, then 6 FMA blocks
            Row<D> a0 = load_row<D>(xp0 + roff[j], rv[j], lv, rvx);
            Row<D> a1 = load_row<D>(xp1 + roff[j], rv[j], lv, rvx);
            fma4<D, 0>(acc0, wg[j * 3 + 0], a0);
            fma4<D, 1>(acc0, wg[j * 3 + 1], a0);
            fma4<D, 2>(acc0, wg[j * 3 + 2], a0);
            fma4<D, 0>(acc1, wg[j * 3 + 0], a1);
            fma4<D, 1>(acc1, wg[j * 3 + 1], a1);
            fma4<D, 2>(acc1, wg[j * 3 + 2], a1);
        }
        *(float4*)(ob + (size_t)g * WC_N * HW)       = acc0;
        *(float4*)(ob + (size_t)(g + 1) * WC_N * HW) = acc1;
    }
}

__global__ __launch_bounds__(NTHR, 4)
void lcd_kernel(const float* __restrict__ x,
                const float* __restrict__ weight,
                const int*   __restrict__ dilation,
                float*       __restrict__ out)
{
    const int idx = blockIdx.x * NTHR + threadIdx.x;  // wc*784 + p4, exact cover
    const int b   = blockIdx.y;
    const int wc  = idx / P4;
    const int p4i = idx - wc * P4;
    const int h   = p4i / W4N;
    const int w4  = (p4i - h * W4N) * 4;
    const int d   = __ldg(&dilation[wc]);   // 1..4

    switch (d) {
        case 1:  lcd_body<1>(x, weight, out, b, wc, h, w4); break;
        case 2:  lcd_body<2>(x, weight, out, b, wc, h, w4); break;
        case 3:  lcd_body<3>(x, weight, out, b, wc, h, w4); break;
        default: lcd_body<4>(x, weight, out, b, wc, h, w4); break;
    }
}

extern "C" void kernel_launch(void* const* d_in, const int* in_sizes, int n_in,
                              void* d_out, int out_size)
{
    const float* x        = (const float*)d_in[0];
    const float* weight   = (const float*)d_in[1];
    const int*   dilation = (const int*)d_in[2];
    float*       out      = (float*)d_out;

    dim3 grid((WC_N * P4) / NTHR, 8);   // (98, 8) — exact cover, no tail
    dim3 block(NTHR);
    lcd_kernel<<<grid, block>>>(x, weight, dilation, out);
}

// round 10
// speedup vs baseline: 1.3821x; 1.3821x over previous
#include <cuda_runtime.h>

#define W56   56
#define HW    3136
#define WC_N  32
#define C_N   256
#define GRP   8
#define NTHR  256
#define W4N   14               // float4 per row
#define P4    (W56 * W4N)      // 784 float4-pixels per (b,c) image

__device__ __forceinline__ float4 zf4() { return make_float4(0.f, 0.f, 0.f, 0.f); }
__device__ __forceinline__ float2 zf2() { return make_float2(0.f, 0.f); }

template<int I>
__device__ __forceinline__ float comp(const float4& v) {
    if constexpr (I == 0) return v.x;
    else if constexpr (I == 1) return v.y;
    else if constexpr (I == 2) return v.z;
    else return v.w;
}

// One x-row window around [w4, w4+4): indices [4-D, 7+D] of a virtual 12-float
// span starting at w4-4. Edges: D=1 -> scalar loads, D=2 -> float2, D>=3 -> float4.
template<int D>
struct Row {
    float4 M;
    float4 L, R;     // D >= 3
    float2 Lh, Rh;   // D == 2
    float  Ls, Rs;   // D == 1
    template<int I>
    __device__ __forceinline__ float get() const {
        if constexpr (I >= 4 && I < 8) return comp<I - 4>(M);
        else if constexpr (I < 4) {
            if constexpr (D == 1)      return Ls;                   // only I==3
            else if constexpr (D == 2) return (I == 2) ? Lh.x : Lh.y;
            else                       return comp<I>(L);
        } else {
            if constexpr (D == 1)      return Rs;                   // only I==8
            else if constexpr (D == 2) return (I == 8) ? Rh.x : Rh.y;
            else                       return comp<I - 8>(R);
        }
    }
};

template<int D>
__device__ __forceinline__ Row<D> load_row(const float* r, bool v, bool lv, bool rvx) {
    Row<D> o;
    o.M = v ? *(const float4*)r : zf4();
    if constexpr (D == 1) {
        o.Ls = (v && lv)  ? r[-1] : 0.f;
        o.Rs = (v && rvx) ? r[4]  : 0.f;
    } else if constexpr (D == 2) {
        o.Lh = (v && lv)  ? *(const float2*)(r - 2) : zf2();
        o.Rh = (v && rvx) ? *(const float2*)(r + 4) : zf2();
    } else {
        o.L = (v && lv)  ? *(const float4*)(r - 4) : zf4();
        o.R = (v && rvx) ? *(const float4*)(r + 4) : zf4();
    }
    return o;
}

template<int D, int KW>
__device__ __forceinline__ void fma4(float4& acc, const float4& wk, const Row<D>& a) {
    constexpr int c = (KW - 1) * D;
    acc.x += wk.x * a.template get<4 + 0 + c>();
    acc.y += wk.y * a.template get<4 + 1 + c>();
    acc.z += wk.z * a.template get<4 + 2 + c>();
    acc.w += wk.w * a.template get<4 + 3 + c>();
}

template<int D>
__device__ __forceinline__ void lcd_body(const float* __restrict__ x,
                                         const float* __restrict__ weight,
                                         float* __restrict__ out,
                                         int b, int wc, int h, int w4)
{
    // 9 taps × 4 pixels of weights in registers, reused across all 8 channel groups
    float4 wg[9];
    {
        const float* wp = weight + ((size_t)(b * WC_N + wc) * 9) * HW + h * W56 + w4;
#pragma unroll
        for (int k = 0; k < 9; k++) wg[k] = *(const float4*)(wp + k * HW);
    }

    const bool lv = (w4 > 0), rvx = (w4 < 52);
    bool rv[3];
    int  roff[3];
#pragma unroll
    for (int j = 0; j < 3; j++) {
        const int hh = h + (j - 1) * D;
        rv[j]   = (unsigned)hh < (unsigned)W56;
        roff[j] = hh * W56 + w4;
    }

    const float* xb = x   + (size_t)(b * C_N + wc) * HW;
    float*       ob = out + (size_t)(b * C_N + wc) * HW + h * W56 + w4;

#pragma unroll 1
    for (int g = 0; g < GRP; g += 2) {
        const float* xp0 = xb + (size_t)g * WC_N * HW;
        const float* xp1 = xp0 + (size_t)WC_N * HW;
        float4 acc0 = zf4(), acc1 = zf4();
#pragma unroll
        for (int j = 0; j < 3; j++) {
            // 6 independent loads (both g-streams) for this tap row, then 6 FMA blocks
            Row<D> a0 = load_row<D>(xp0 + roff[j], rv[j], lv, rvx);
            Row<D> a1 = load_row<D>(xp1 + roff[j], rv[j], lv, rvx);
            fma4<D, 0>(acc0, wg[j * 3 + 0], a0);
            fma4<D, 1>(acc0, wg[j * 3 + 1], a0);
            fma4<D, 2>(acc0, wg[j * 3 + 2], a0);
            fma4<D, 0>(acc1, wg[j * 3 + 0], a1);
            fma4<D, 1>(acc1, wg[j * 3 + 1], a1);
            fma4<D, 2>(acc1, wg[j * 3 + 2], a1);
        }
        *(float4*)(ob + (size_t)g * WC_N * HW)       = acc0;
        *(float4*)(ob + (size_t)(g + 1) * WC_N * HW) = acc1;
    }
}

__global__ __launch_bounds__(NTHR)
void lcd_kernel(const float* __restrict__ x,
                const float* __restrict__ weight,
                const int*   __restrict__ dilation,
                float*       __restrict__ out)
{
    const int idx = blockIdx.x * NTHR + threadIdx.x;  // wc*784 + p4, exact cover
    const int b   = blockIdx.y;
    const int wc  = idx / P4;
    const int p4i = idx - wc * P4;
    const int h   = p4i / W4N;
    const int w4  = (p4i - h * W4N) * 4;
    const int d   = __ldg(&dilation[wc]);   // 1..4

    switch (d) {
        case 1:  lcd_body<1>(x, weight, out, b, wc, h, w4); break;
        case 2:  lcd_body<2>(x, weight, out, b, wc, h, w4); break;
        case 3:  lcd_body<3>(x, weight, out, b, wc, h, w4); break;
        default: lcd_body<4>(x, weight, out, b, wc, h, w4); break;
    }
}

extern "C" void kernel_launch(void* const* d_in, const int* in_sizes, int n_in,
                              void* d_out, int out_size)
{
    const float* x        = (const float*)d_in[0];
    const float* weight   = (const float*)d_in[1];
    const int*   dilation = (const int*)d_in[2];
    float*       out      = (float*)d_out;

    dim3 grid((WC_N * P4) / NTHR, 8);   // (98, 8) — exact cover, no tail
    dim3 block(NTHR);
    lcd_kernel<<<grid, block>>>(x, weight, dilation, out);
}

// round 12
// speedup vs baseline: 1.5255x; 1.1037x over previous
#include <cuda_runtime.h>

#define W56   56
#define HW    3136
#define WC_N  32
#define C_N   256
#define GRP   8
#define LW    16     // lanes per image row (14 active + 2 idle)
#define RPB   14     // rows per block
#define NTHR  (LW * RPB)   // 224

__device__ __forceinline__ float4 zf4() { return make_float4(0.f, 0.f, 0.f, 0.f); }

__device__ __forceinline__ float getc(const float4& v, int i) {
    // always called with compile-time-constant i inside fully unrolled code
    switch (i) { case 0: return v.x; case 1: return v.y; case 2: return v.z; default: return v.w; }
}
__device__ __forceinline__ void addc(float4& v, int i, float a) {
    switch (i) { case 0: v.x += a; break; case 1: v.y += a; break;
                 case 2: v.z += a; break; default: v.w += a; break; }
}

// Logical 12-float window [w4-4, w4+8) around this lane's M = x[row, w4..w4+4).
// Indices 0..3 live in the prev lane's M, 8..11 in the next lane's M; only the
// D nearest on each side are ever used -> 2*D shfls.
template<int D>
struct Win {
    float4 M;
    float  Lc[4];   // Lc[k] = pixel w4 - D + k   (k = 0..D-1)
    float  Rc[4];   // Rc[k] = pixel w4 + 4 + k   (k = 0..D-1)
};

template<int D>
__device__ __forceinline__ Win<D> make_win(float4 M, bool lv, bool rvx) {
    Win<D> w; w.M = M;
#pragma unroll
    for (int k = 0; k < D; k++) {
        float l = __shfl_up_sync  (0xffffffffu, getc(M, 4 - D + k), 1, LW);
        float r = __shfl_down_sync(0xffffffffu, getc(M, k),         1, LW);
        w.Lc[k] = lv  ? l : 0.f;
        w.Rc[k] = rvx ? r : 0.f;
    }
    return w;
}

template<int D>
__device__ __forceinline__ float wat(const Win<D>& w, int I) {   // I constant
    if (I < 4)      return w.Lc[I - (4 - D)];
    else if (I < 8) return getc(w.M, I - 4);
    else            return w.Rc[I - 8];
}

template<int D>
__device__ __forceinline__ void fma4(float4& acc, const float4& wk, const Win<D>& a, int c) {
#pragma unroll
    for (int i = 0; i < 4; i++)
        addc(acc, i, getc(wk, i) * wat<D>(a, 4 + i + c));
}

template<int D>
__device__ __forceinline__ void lcd_body(const float* __restrict__ x,
                                         const float* __restrict__ weight,
                                         float* __restrict__ out,
                                         int b, int wc, int h, int w4, bool active)
{
    // 9 taps x 4 pixels of weights in registers, reused across all 8 channel groups
    float4 wg[9];
    if (active) {
        const float* wp = weight + ((size_t)(b * WC_N + wc) * 9) * HW + h * W56 + w4;
#pragma unroll
        for (int k = 0; k < 9; k++) wg[k] = *(const float4*)(wp + k * HW);
    } else {
#pragma unroll
        for (int k = 0; k < 9; k++) wg[k] = zf4();
    }

    const bool lv = (w4 > 0), rvx = (w4 < 52);
    bool rv[3];
    int  roff[3];
#pragma unroll
    for (int j = 0; j < 3; j++) {
        const int hh = h + (j - 1) * D;
        rv[j]   = ((unsigned)hh < (unsigned)W56) && active;
        roff[j] = hh * W56 + w4;
    }

    const float* xb = x   + (size_t)(b * C_N + wc) * HW;
    float*       ob = out + (size_t)(b * C_N + wc) * HW + h * W56 + w4;

#pragma unroll 1
    for (int g = 0; g < GRP; g += 2) {
        const float* xp0 = xb + (size_t)g * WC_N * HW;
        const float* xp1 = xp0 + (size_t)WC_N * HW;
        float4 acc0 = zf4(), acc1 = zf4();

        // front-batch 6 independent LDG.128 (both g-streams, 3 tap rows)
        float4 M0[3], M1[3];
#pragma unroll
        for (int j = 0; j < 3; j++) {
            M0[j] = rv[j] ? *(const float4*)(xp0 + roff[j]) : zf4();
            M1[j] = rv[j] ? *(const float4*)(xp1 + roff[j]) : zf4();
        }
#pragma unroll
        for (int j = 0; j < 3; j++) {
            Win<D> a0 = make_win<D>(M0[j], lv, rvx);
            Win<D> a1 = make_win<D>(M1[j], lv, rvx);
#pragma unroll
            for (int kw = 0; kw < 3; kw++) {
                const int c = (kw - 1) * D;
                fma4<D>(acc0, wg[j * 3 + kw], a0, c);
                fma4<D>(acc1, wg[j * 3 + kw], a1, c);
            }
        }
        if (active) {
            *(float4*)(ob + (size_t)g * WC_N * HW)       = acc0;
            *(float4*)(ob + (size_t)(g + 1) * WC_N * HW) = acc1;
        }
    }
}

__global__ __launch_bounds__(NTHR)
void lcd_kernel(const float* __restrict__ x,
                const float* __restrict__ weight,
                const int*   __restrict__ dilation,
                float*       __restrict__ out)
{
    const int tx = threadIdx.x;            // 0..15 (lane within row)
    const int ty = threadIdx.y;            // 0..13 (row within strip)
    const int wc = blockIdx.y;
    const int b  = blockIdx.z;
    const int h  = blockIdx.x * RPB + ty;  // 0..55
    const int w4 = tx * 4;
    const bool active = (tx < 14);

    const int d = __ldg(&dilation[wc]);    // 1..4, uniform per block -> no divergence

    switch (d) {
        case 1:  lcd_body<1>(x, weight, out, b, wc, h, w4, active); break;
        case 2:  lcd_body<2>(x, weight, out, b, wc, h, w4, active); break;
        case 3:  lcd_body<3>(x, weight, out, b, wc, h, w4, active); break;
        default: lcd_body<4>(x, weight, out, b, wc, h, w4, active); break;
    }
}

extern "C" void kernel_launch(void* const* d_in, const int* in_sizes, int n_in,
                              void* d_out, int out_size)
{
    const float* x        = (const float*)d_in[0];
    const float* weight   = (const float*)d_in[1];
    const int*   dilation = (const int*)d_in[2];
    float*       out      = (float*)d_out;

    dim3 grid(W56 / RPB, WC_N, 8);   // (4, 32, 8)
    dim3 block(LW, RPB);             // 224 threads
    lcd_kernel<<<grid, block>>>(x, weight, dilation, out);
}